// round 2
// baseline (speedup 1.0000x reference)
#include <cuda_runtime.h>
#include <cstdint>

#define BB 128
#define SS 512
#define EE 512
#define HH 1024
#define TOK (BB*SS)

// Scratch (allocation-free rule: __device__ globals)
__device__ float g_pre[(size_t)TOK * HH];   // [s*B + b][h], fp32, 256 MB
__device__ float g_h[2][BB * HH];           // ping-pong hidden state

__device__ __forceinline__ unsigned f2tf(float f){
  unsigned u; asm("cvt.rna.tf32.f32 %0, %1;" : "=r"(u) : "f"(f)); return u;
}

__device__ __forceinline__ void mma8(float c[4], unsigned a0,unsigned a1,unsigned a2,unsigned a3,
                                     unsigned b0,unsigned b1){
  asm volatile("mma.sync.aligned.m16n8k8.row.col.f32.tf32.tf32.f32 "
    "{%0,%1,%2,%3}, {%4,%5,%6,%7}, {%8,%9}, {%0,%1,%2,%3};"
    : "+f"(c[0]),"+f"(c[1]),"+f"(c[2]),"+f"(c[3])
    : "r"(a0),"r"(a1),"r"(a2),"r"(a3),"r"(b0),"r"(b1));
}

__global__ void k_init(){
  int i = blockIdx.x*blockDim.x + threadIdx.x;
  if (i < BB*HH) g_h[0][i] = 0.f;
}

// pre[s*B+b][h] = dot(emb[x[b][s]], W[h]) + Wb[h]   (M=65536, N=1024, K=512)
// Tiles: BM=64, BN=64, BK=32, 256 threads, tf32 mma (single, RNA-rounded).
__global__ __launch_bounds__(256) void k_pre(const int* __restrict__ x, const float* __restrict__ emb,
                                             const float* __restrict__ Ww, const float* __restrict__ Wb){
  __shared__ unsigned As[64][33];
  __shared__ unsigned Bsm[64][33];
  __shared__ const float* rowp[64];
  const int tid = threadIdx.x;
  const int m0 = blockIdx.y*64, n0 = blockIdx.x*64;
  if (tid < 64){
    int tok = m0 + tid;
    int b = tok & (BB-1), s = tok >> 7;
    rowp[tid] = emb + (size_t)x[b*SS + s]*EE;
  }
  __syncthreads();
  const int lane = tid & 31, wid = tid >> 5;
  const int wm = wid >> 1, wn = wid & 1;         // 4x2 warp grid, warp tile 16x32
  const int gr = lane >> 2, gq = lane & 3;
  float acc[4][4];
  #pragma unroll
  for (int i=0;i<4;i++){ acc[i][0]=0.f; acc[i][1]=0.f; acc[i][2]=0.f; acc[i][3]=0.f; }

  for (int kt = 0; kt < EE/32; ++kt){
    const int k0 = kt*32;
    #pragma unroll
    for (int it=0; it<2; ++it){
      int id = tid + it*256;
      int r = id >> 3, c4 = (id & 7)*4;
      float4 v = *(const float4*)(rowp[r] + k0 + c4);
      As[r][c4+0]=f2tf(v.x); As[r][c4+1]=f2tf(v.y); As[r][c4+2]=f2tf(v.z); As[r][c4+3]=f2tf(v.w);
      float4 w = *(const float4*)(Ww + (size_t)(n0+r)*EE + k0 + c4);
      Bsm[r][c4+0]=f2tf(w.x); Bsm[r][c4+1]=f2tf(w.y); Bsm[r][c4+2]=f2tf(w.z); Bsm[r][c4+3]=f2tf(w.w);
    }
    __syncthreads();
    #pragma unroll
    for (int kk=0; kk<4; ++kk){
      unsigned a0 = As[wm*16+gr  ][kk*8+gq];
      unsigned a1 = As[wm*16+gr+8][kk*8+gq];
      unsigned a2 = As[wm*16+gr  ][kk*8+gq+4];
      unsigned a3 = As[wm*16+gr+8][kk*8+gq+4];
      #pragma unroll
      for (int nf=0; nf<4; ++nf){
        int nr = wn*32 + nf*8 + gr;
        mma8(acc[nf], a0,a1,a2,a3, Bsm[nr][kk*8+gq], Bsm[nr][kk*8+gq+4]);
      }
    }
    __syncthreads();
  }
  #pragma unroll
  for (int nf=0; nf<4; ++nf){
    int nc = n0 + wn*32 + nf*8 + 2*gq;
    int mr = m0 + wm*16 + gr;
    float wb0 = Wb[nc], wb1 = Wb[nc+1];
    g_pre[(size_t)mr*HH + nc]        = acc[nf][0] + wb0;
    g_pre[(size_t)mr*HH + nc + 1]    = acc[nf][1] + wb1;
    g_pre[(size_t)(mr+8)*HH + nc]    = acc[nf][2] + wb0;
    g_pre[(size_t)(mr+8)*HH + nc+1]  = acc[nf][3] + wb1;
  }
}

// One recurrence step: h_new = tanh(pre_t + h_old @ U^T + Ub)
// M=128, N=1024, K=1024. BM=32, BN=32 -> 128 CTAs. cp.async 4-stage pipeline.
// A (h) is split hi/lo tf32 (full fp32 precision in the product); U single tf32-RNA.
#define NT (HH/32)
__global__ __launch_bounds__(128) void k_step(const float* __restrict__ U, const float* __restrict__ Ub, int t){
  __shared__ float As[4][32][36];
  __shared__ float Bsm[4][32][36];
  const float* __restrict__ hold = g_h[t & 1];
  float* __restrict__ hnew = g_h[(t & 1) ^ 1];
  const float* __restrict__ pre = g_pre + (size_t)t*BB*HH;
  const int tid = threadIdx.x, lane = tid & 31, wid = tid >> 5;
  const int wm = wid >> 1, wn = wid & 1;          // 2x2 warp grid, warp tile 16x16
  const int gr = lane >> 2, gq = lane & 3;
  const int n0 = blockIdx.x*32, m0 = blockIdx.y*32;

  float acc[2][4];
  acc[0][0]=0.f;acc[0][1]=0.f;acc[0][2]=0.f;acc[0][3]=0.f;
  acc[1][0]=0.f;acc[1][1]=0.f;acc[1][2]=0.f;acc[1][3]=0.f;

  auto issue = [&](int kt){
    int stage = kt & 3;
    int k0 = kt*32;
    #pragma unroll
    for (int it=0; it<2; ++it){
      int id = tid + it*128;
      int r = id >> 3, c4 = (id & 7)*4;
      uint32_t sa = (uint32_t)__cvta_generic_to_shared(&As[stage][r][c4]);
      const float* ga = hold + (size_t)(m0+r)*HH + k0 + c4;
      asm volatile("cp.async.cg.shared.global [%0], [%1], 16;" :: "r"(sa), "l"(ga));
      uint32_t sb = (uint32_t)__cvta_generic_to_shared(&Bsm[stage][r][c4]);
      const float* gb = U + (size_t)(n0+r)*HH + k0 + c4;
      asm volatile("cp.async.cg.shared.global [%0], [%1], 16;" :: "r"(sb), "l"(gb));
    }
  };

  for (int p=0; p<3; ++p){ issue(p); asm volatile("cp.async.commit_group;"); }

  for (int kt=0; kt<NT; ++kt){
    if (kt+3 < NT) issue(kt+3);
    asm volatile("cp.async.commit_group;");
    asm volatile("cp.async.wait_group 3;" ::: "memory");
    __syncthreads();
    const int st = kt & 3;
    #pragma unroll
    for (int kk=0; kk<4; ++kk){
      float av0 = As[st][wm*16+gr  ][kk*8+gq];
      float av1 = As[st][wm*16+gr+8][kk*8+gq];
      float av2 = As[st][wm*16+gr  ][kk*8+gq+4];
      float av3 = As[st][wm*16+gr+8][kk*8+gq+4];
      unsigned ah0=f2tf(av0), ah1=f2tf(av1), ah2=f2tf(av2), ah3=f2tf(av3);
      unsigned al0=f2tf(av0-__uint_as_float(ah0));
      unsigned al1=f2tf(av1-__uint_as_float(ah1));
      unsigned al2=f2tf(av2-__uint_as_float(ah2));
      unsigned al3=f2tf(av3-__uint_as_float(ah3));
      #pragma unroll
      for (int nf=0; nf<2; ++nf){
        int nr = wn*16 + nf*8 + gr;
        unsigned b0 = f2tf(Bsm[st][nr][kk*8+gq]);
        unsigned b1 = f2tf(Bsm[st][nr][kk*8+gq+4]);
        mma8(acc[nf], ah0,ah1,ah2,ah3, b0,b1);
        mma8(acc[nf], al0,al1,al2,al3, b0,b1);
      }
    }
    __syncthreads();
  }
  #pragma unroll
  for (int nf=0; nf<2; ++nf){
    int nc = n0 + wn*16 + nf*8 + 2*gq;
    int mr = m0 + wm*16 + gr;
    float ub0 = Ub[nc], ub1 = Ub[nc+1];
    hnew[(size_t)mr*HH+nc]       = tanhf(acc[nf][0] + pre[(size_t)mr*HH+nc]       + ub0);
    hnew[(size_t)mr*HH+nc+1]     = tanhf(acc[nf][1] + pre[(size_t)mr*HH+nc+1]     + ub1);
    hnew[(size_t)(mr+8)*HH+nc]   = tanhf(acc[nf][2] + pre[(size_t)(mr+8)*HH+nc]   + ub0);
    hnew[(size_t)(mr+8)*HH+nc+1] = tanhf(acc[nf][3] + pre[(size_t)(mr+8)*HH+nc+1] + ub1);
  }
}

__global__ void k_final(const float* __restrict__ Vw, const float* __restrict__ Vb, float* __restrict__ out){
  int b = blockIdx.x;
  const float* h = g_h[0] + (size_t)b*HH;   // after 512 steps, result sits in g_h[0]
  float s = 0.f;
  for (int k = threadIdx.x; k < HH; k += 128) s += h[k]*Vw[k];
  #pragma unroll
  for (int o=16;o;o>>=1) s += __shfl_down_sync(0xffffffffu, s, o);
  __shared__ float red[4];
  if ((threadIdx.x & 31) == 0) red[threadIdx.x>>5] = s;
  __syncthreads();
  if (threadIdx.x == 0){
    float tot = red[0]+red[1]+red[2]+red[3] + Vb[0];
    out[b] = 1.f/(1.f + expf(-tot));
  }
}

extern "C" void kernel_launch(void* const* d_in, const int* in_sizes, int n_in,
                              void* d_out, int out_size){
  (void)in_sizes; (void)n_in; (void)out_size;
  const int*   x   = (const int*)d_in[0];
  const float* emb = (const float*)d_in[1];
  const float* Ww  = (const float*)d_in[2];
  const float* Wb  = (const float*)d_in[3];
  const float* Uw  = (const float*)d_in[4];
  const float* Ubv = (const float*)d_in[5];
  const float* Vw  = (const float*)d_in[6];
  const float* Vb  = (const float*)d_in[7];
  float* out = (float*)d_out;

  k_init<<<(BB*HH+255)/256, 256>>>();
  k_pre<<<dim3(HH/64, TOK/64), 256>>>(x, emb, Ww, Wb);
  for (int t=0; t<SS; ++t)
    k_step<<<dim3(HH/32, BB/32), 128>>>(Uw, Ubv, t);
  k_final<<<BB, 128>>>(Vw, Vb, out);
}

// round 4
// speedup vs baseline: 1.2165x; 1.2165x over previous
#include <cuda_runtime.h>
#include <cstdint>

#define BB 128
#define SS 512
#define EE 512
#define HH 1024
#define TOK (BB*SS)
#define NCTA 128

// Scratch (allocation-free rule: __device__ globals)
__device__ float g_pre[(size_t)TOK * HH];   // [s*B + b][h], fp32
__device__ float g_h[2][BB * HH];           // ping-pong hidden state
__device__ unsigned g_cnt;                  // monotonic barrier counter

__device__ __forceinline__ unsigned f2tf(float f){
  unsigned u; asm("cvt.rna.tf32.f32 %0, %1;" : "=r"(u) : "f"(f)); return u;
}

__device__ __forceinline__ void mma8(float c[4], unsigned a0,unsigned a1,unsigned a2,unsigned a3,
                                     unsigned b0,unsigned b1){
  asm volatile("mma.sync.aligned.m16n8k8.row.col.f32.tf32.tf32.f32 "
    "{%0,%1,%2,%3}, {%4,%5,%6,%7}, {%8,%9}, {%0,%1,%2,%3};"
    : "+f"(c[0]),"+f"(c[1]),"+f"(c[2]),"+f"(c[3])
    : "r"(a0),"r"(a1),"r"(a2),"r"(a3),"r"(b0),"r"(b1));
}

__global__ void k_init(){
  int i = blockIdx.x*blockDim.x + threadIdx.x;
  if (i < BB*HH) g_h[0][i] = 0.f;
  if (i == 0){ g_cnt = 0u; }
}

// pre[s*B+b][h] = dot(emb[x[b][s]], W[h]) + Wb[h]   (M=65536, N=1024, K=512)
__global__ __launch_bounds__(256) void k_pre(const int* __restrict__ x, const float* __restrict__ emb,
                                             const float* __restrict__ Ww, const float* __restrict__ Wb){
  __shared__ unsigned As[64][33];
  __shared__ unsigned Bsm[64][33];
  __shared__ const float* rowp[64];
  const int tid = threadIdx.x;
  const int m0 = blockIdx.y*64, n0 = blockIdx.x*64;
  if (tid < 64){
    int tok = m0 + tid;
    int b = tok & (BB-1), s = tok >> 7;
    rowp[tid] = emb + (size_t)x[b*SS + s]*EE;
  }
  __syncthreads();
  const int lane = tid & 31, wid = tid >> 5;
  const int wm = wid >> 1, wn = wid & 1;
  const int gr = lane >> 2, gq = lane & 3;
  float acc[4][4];
  #pragma unroll
  for (int i=0;i<4;i++){ acc[i][0]=0.f; acc[i][1]=0.f; acc[i][2]=0.f; acc[i][3]=0.f; }

  for (int kt = 0; kt < EE/32; ++kt){
    const int k0 = kt*32;
    #pragma unroll
    for (int it=0; it<2; ++it){
      int id = tid + it*256;
      int r = id >> 3, c4 = (id & 7)*4;
      float4 v = *(const float4*)(rowp[r] + k0 + c4);
      As[r][c4+0]=f2tf(v.x); As[r][c4+1]=f2tf(v.y); As[r][c4+2]=f2tf(v.z); As[r][c4+3]=f2tf(v.w);
      float4 w = *(const float4*)(Ww + (size_t)(n0+r)*EE + k0 + c4);
      Bsm[r][c4+0]=f2tf(w.x); Bsm[r][c4+1]=f2tf(w.y); Bsm[r][c4+2]=f2tf(w.z); Bsm[r][c4+3]=f2tf(w.w);
    }
    __syncthreads();
    #pragma unroll
    for (int kk=0; kk<4; ++kk){
      unsigned a0 = As[wm*16+gr  ][kk*8+gq];
      unsigned a1 = As[wm*16+gr+8][kk*8+gq];
      unsigned a2 = As[wm*16+gr  ][kk*8+gq+4];
      unsigned a3 = As[wm*16+gr+8][kk*8+gq+4];
      #pragma unroll
      for (int nf=0; nf<4; ++nf){
        int nr = wn*32 + nf*8 + gr;
        mma8(acc[nf], a0,a1,a2,a3, Bsm[nr][kk*8+gq], Bsm[nr][kk*8+gq+4]);
      }
    }
    __syncthreads();
  }
  #pragma unroll
  for (int nf=0; nf<4; ++nf){
    int nc = n0 + wn*32 + nf*8 + 2*gq;
    int mr = m0 + wm*16 + gr;
    float wb0 = Wb[nc], wb1 = Wb[nc+1];
    g_pre[(size_t)mr*HH + nc]        = acc[nf][0] + wb0;
    g_pre[(size_t)mr*HH + nc + 1]    = acc[nf][1] + wb1;
    g_pre[(size_t)(mr+8)*HH + nc]    = acc[nf][2] + wb0;
    g_pre[(size_t)(mr+8)*HH + nc+1]  = acc[nf][3] + wb1;
  }
}

// ---------------- persistent recurrence kernel (simple, all-warp) ----------------
// 128 CTAs = 4 (M, 32 rows) x 32 (N, 32 cols), 256 threads, 8 warps all compute.
// Warp grid: wm = wid&1 (m-half of 16), wn = wid>>1 (n-block of 8). Warp tile 16x8.
// SMEM: Bp = U slice tf32 frag-packed [32768 words], stage = 2 x 32 x 132 raw fp32 h.
#define SM_BP    0
#define SM_STAGE 32768
#define STAGE_WORDS (32*132)
#define SMEM_WORDS (32768 + 2*STAGE_WORDS)

__device__ __forceinline__ void cpa16(unsigned* dst_sm, const float* src){
  uint32_t sa = (uint32_t)__cvta_generic_to_shared(dst_sm);
  asm volatile("cp.async.cg.shared.global [%0], [%1], 16;" :: "r"(sa), "l"(src));
}

__global__ __launch_bounds__(256, 1) void k_scan(const float* __restrict__ U, const float* __restrict__ Ub){
  extern __shared__ unsigned smw[];
  const int tid = threadIdx.x, lane = tid & 31, wid = tid >> 5;
  const int gr = lane >> 2, gq = lane & 3;
  const int wm = wid & 1, wn = wid >> 1;
  const int m0 = blockIdx.y*32, n0 = blockIdx.x*32;

  // ---- pack U slice (rows n0..n0+31 of U, full K) into tf32 B-fragments ----
  // (n,k) -> word ((kg*4 + (n>>3))*32 + (n&7)*4 + (kk&3))*2 + (kk>>2); kg=k>>3, kk=k&7
  for (int e = tid; e < 32*HH; e += 256){
    int n = e >> 10, k = e & (HH-1);
    float v = U[(size_t)(n0+n)*HH + k];
    int kg = k >> 3, kk = k & 7;
    int w = ((kg*4 + (n>>3))*32 + (n&7)*4 + (kk&3))*2 + (kk>>2);
    smw[SM_BP + w] = f2tf(v);
  }
  const int nc = n0 + wn*8 + 2*gq;
  const int mr = m0 + wm*16 + gr;
  const float ub0 = Ub[nc], ub1 = Ub[nc+1];
  __syncthreads();

  for (int t = 0; t < SS; ++t){
    const float* __restrict__ hold = g_h[t & 1];
    float* __restrict__ hnew = g_h[(t & 1) ^ 1];
    const float* __restrict__ pre = g_pre + (size_t)t*BB*HH;

    const float pv0 = pre[(size_t)mr*HH + nc];
    const float pv1 = pre[(size_t)mr*HH + nc + 1];
    const float pv2 = pre[(size_t)(mr+8)*HH + nc];
    const float pv3 = pre[(size_t)(mr+8)*HH + nc + 1];
    float acc[4] = {0.f, 0.f, 0.f, 0.f};

    // prefetch chunk 0 (32 rows x 128 floats) into stage buf 0
    #pragma unroll
    for (int i=0;i<4;++i){
      int idx = tid + i*256; int r = idx >> 5, j = idx & 31;
      cpa16(smw + SM_STAGE + r*132 + j*4, hold + (size_t)(m0+r)*HH + j*4);
    }
    asm volatile("cp.async.commit_group;");

    #pragma unroll 1
    for (int c = 0; c < 8; ++c){
      if (c < 7){
        int buf = (c+1) & 1;
        #pragma unroll
        for (int i=0;i<4;++i){
          int idx = tid + i*256; int r = idx >> 5, j = idx & 31;
          cpa16(smw + SM_STAGE + buf*STAGE_WORDS + r*132 + j*4,
                hold + (size_t)(m0+r)*HH + (c+1)*128 + j*4);
        }
        asm volatile("cp.async.commit_group;");
        asm volatile("cp.async.wait_group 1;" ::: "memory");
      } else {
        asm volatile("cp.async.wait_group 0;" ::: "memory");
      }
      __syncthreads();

      const float* st = (const float*)(smw + SM_STAGE + (c&1)*STAGE_WORDS) + (wm*16+gr)*132 + gq;
      const unsigned* bp = smw + SM_BP + c*4096 + (wn*32 + lane)*2;
      #pragma unroll
      for (int kb = 0; kb < 16; ++kb){
        float v0 = st[kb*8];
        float v1 = st[kb*8 + 8*132];
        float v2 = st[kb*8 + 4];
        float v3 = st[kb*8 + 4 + 8*132];
        unsigned h0=f2tf(v0), h1=f2tf(v1), h2=f2tf(v2), h3=f2tf(v3);
        unsigned l0=f2tf(v0-__uint_as_float(h0));
        unsigned l1=f2tf(v1-__uint_as_float(h1));
        unsigned l2=f2tf(v2-__uint_as_float(h2));
        unsigned l3=f2tf(v3-__uint_as_float(h3));
        uint2 bb = *(const uint2*)(bp + kb*256);
        mma8(acc, h0,h1,h2,h3, bb.x, bb.y);
        mma8(acc, l0,l1,l2,l3, bb.x, bb.y);
      }
      __syncthreads();
    }

    // epilogue: h_new = tanh(acc + pre + Ub)
    float2 o0, o1;
    o0.x = tanhf(acc[0] + pv0 + ub0);
    o0.y = tanhf(acc[1] + pv1 + ub1);
    o1.x = tanhf(acc[2] + pv2 + ub0);
    o1.y = tanhf(acc[3] + pv3 + ub1);
    *(float2*)&hnew[(size_t)mr*HH + nc]     = o0;
    *(float2*)&hnew[(size_t)(mr+8)*HH + nc] = o1;

    // monotonic global barrier across 128 CTAs (skip after last step)
    if (t < SS-1){
      __threadfence();
      __syncthreads();
      if (tid == 0){
        atomicAdd(&g_cnt, 1u);
        const unsigned target = (unsigned)(t+1) * NCTA;
        volatile unsigned* vc = &g_cnt;
        while (*vc < target) { }
      }
      __syncthreads();
      __threadfence();
    }
  }
}

__global__ void k_final(const float* __restrict__ Vw, const float* __restrict__ Vb, float* __restrict__ out){
  int b = blockIdx.x;
  const float* h = g_h[0] + (size_t)b*HH;   // after 512 steps, result sits in g_h[0]
  float s = 0.f;
  for (int k = threadIdx.x; k < HH; k += 128) s += h[k]*Vw[k];
  #pragma unroll
  for (int o=16;o;o>>=1) s += __shfl_down_sync(0xffffffffu, s, o);
  __shared__ float red[4];
  if ((threadIdx.x & 31) == 0) red[threadIdx.x>>5] = s;
  __syncthreads();
  if (threadIdx.x == 0){
    float tot = red[0]+red[1]+red[2]+red[3] + Vb[0];
    out[b] = 1.f/(1.f + expf(-tot));
  }
}

extern "C" void kernel_launch(void* const* d_in, const int* in_sizes, int n_in,
                              void* d_out, int out_size){
  (void)in_sizes; (void)n_in; (void)out_size;
  const int*   x   = (const int*)d_in[0];
  const float* emb = (const float*)d_in[1];
  const float* Ww  = (const float*)d_in[2];
  const float* Wb  = (const float*)d_in[3];
  const float* Uw  = (const float*)d_in[4];
  const float* Ubv = (const float*)d_in[5];
  const float* Vw  = (const float*)d_in[6];
  const float* Vb  = (const float*)d_in[7];
  float* out = (float*)d_out;

  static bool attr_done = false;
  if (!attr_done){
    cudaFuncSetAttribute(k_scan, cudaFuncAttributeMaxDynamicSharedMemorySize, SMEM_WORDS*4);
    attr_done = true;
  }

  k_init<<<(BB*HH+255)/256, 256>>>();
  k_pre<<<dim3(HH/64, TOK/64), 256>>>(x, emb, Ww, Wb);
  k_scan<<<dim3(32, 4), 256, SMEM_WORDS*4>>>(Uw, Ubv);
  k_final<<<BB, 128>>>(Vw, Vb, out);
}